// round 12
// baseline (speedup 1.0000x reference)
#include <cuda_runtime.h>
#include <cuda_fp16.h>
#include <math.h>
#include <stdint.h>

#define S_LEN 4096
#define B_DIM 32
#define H_DIM 512
#define NROW  (S_LEN * B_DIM)   // 131072
#define NUNITS 4096             // 32-row work units

// ---------------- device scratch ----------------
__device__ __half g_Bh[H_DIM * H_DIM];   // fp16 hi(W[k][n]) transposed [n][k]
__device__ __half g_Bl[H_DIM * H_DIM];   // fp16 lo
__device__ unsigned g_cnt;               // shared work counter (reset by split_w)

__device__ __forceinline__ uint32_t smem_u32(const void* p) {
    uint32_t a;
    asm("{ .reg .u64 t; cvta.to.shared.u64 t, %1; cvt.u32.u64 %0, t; }" : "=r"(a) : "l"(p));
    return a;
}

#define LDSM4(r0, r1, r2, r3, addr) \
    asm volatile("ldmatrix.sync.aligned.m8n8.x4.shared.b16 {%0,%1,%2,%3}, [%4];" \
        : "=r"(r0), "=r"(r1), "=r"(r2), "=r"(r3) : "r"(addr))

#define MMA16816(c, a, b0, b1) \
    asm volatile("mma.sync.aligned.m16n8k16.row.col.f32.f16.f16.f32 " \
        "{%0,%1,%2,%3}, {%4,%5,%6,%7}, {%8,%9}, {%0,%1,%2,%3};" \
        : "+f"((c)[0]), "+f"((c)[1]), "+f"((c)[2]), "+f"((c)[3]) \
        : "r"((a)[0]), "r"((a)[1]), "r"((a)[2]), "r"((a)[3]), "r"(b0), "r"(b1))

// packed fp32x2 helpers (FFMA2 path)
__device__ __forceinline__ unsigned long long pk2(float x, float y) {
    unsigned long long r;
    asm("mov.b64 %0, {%1, %2};" : "=l"(r) : "f"(x), "f"(y));
    return r;
}
__device__ __forceinline__ void fma2(unsigned long long &d, unsigned long long a, unsigned long long b) {
    asm("fma.rn.f32x2 %0, %1, %2, %0;" : "+l"(d) : "l"(a), "l"(b));
}
__device__ __forceinline__ float2 up2(unsigned long long v) {
    float2 r;
    asm("mov.b64 {%0, %1}, %2;" : "=f"(r.x), "=f"(r.y) : "l"(v));
    return r;
}

__device__ __forceinline__ void split4(float4 v, uint2& hi, uint2& lo) {
    __half2 h01 = __floats2half2_rn(v.x, v.y);
    __half2 h23 = __floats2half2_rn(v.z, v.w);
    float2 f01 = __half22float2(h01);
    float2 f23 = __half22float2(h23);
    __half2 l01 = __floats2half2_rn(v.x - f01.x, v.y - f01.y);
    __half2 l23 = __floats2half2_rn(v.z - f23.x, v.w - f23.y);
    hi.x = *(uint32_t*)&h01; hi.y = *(uint32_t*)&h23;
    lo.x = *(uint32_t*)&l01; lo.y = *(uint32_t*)&l23;
}

// ---------------- kernel 0: split W (transposed) + counter reset -------------
__global__ __launch_bounds__(256) void split_w(const float* __restrict__ Wm) {
    if (blockIdx.x == 0 && threadIdx.x == 0) g_cnt = 0;
    int idx = blockIdx.x * 256 + threadIdx.x;   // 0 .. 262143
    int k = idx >> 9, n = idx & 511;
    float v = Wm[idx];
    __half hi = __float2half_rn(v);
    g_Bh[n * H_DIM + k] = hi;
    g_Bl[n * H_DIM + k] = __float2half_rn(v - __half2float(hi));
}

// ---------------- tensor kernel: persistent 3xFP16 HMMA (R6 body) ------------
// SMEM per buffer: 4 tiles (A_hi, A_lo, B_hi, B_lo), 128 rows x 40 halfs (80B)
#define TSTRIDE_B 80
#define TILE_B    (128 * TSTRIDE_B)   // 10240
#define BUF_B     (4 * TILE_B)        // 40960
#define SMEM_TOTAL (2 * BUF_B)        // 81920

__global__ __launch_bounds__(256, 1) void bilinear_hmma_ws(
    const float* __restrict__ enc, const float* __restrict__ hid,
    float* __restrict__ logits)
{
    extern __shared__ char smem[];
    __shared__ unsigned s_u;
    const uint32_t sb = smem_u32(smem);
    const int tid = threadIdx.x;
    const int lane = tid & 31, wid = tid >> 5;
    const int warp_m = wid >> 2;     // 0..1 : m offset 64*warp_m
    const int warp_n = wid & 3;      // 0..3 : n offset 32*warp_n

    const int rrow = tid >> 3;           // 0..31
    const int c4   = (tid & 7) * 4;      // 0,4,..,28
    uint32_t asts[4];
#pragma unroll
    for (int i = 0; i < 4; ++i)
        asts[i] = (uint32_t)((rrow + i * 32) * TSTRIDE_B + c4 * 2);

    uint32_t a_addr[4];
#pragma unroll
    for (int mt = 0; mt < 4; ++mt)
        a_addr[mt] = sb + (uint32_t)((warp_m * 64 + mt * 16 + (lane & 15)) * TSTRIDE_B
                                     + ((lane >> 4) & 1) * 16);
    uint32_t b_addr[2];
#pragma unroll
    for (int p = 0; p < 2; ++p)
        b_addr[p] = sb + 2 * TILE_B +
                    (uint32_t)((warp_n * 32 + p * 16 + (lane & 15)) * TSTRIDE_B
                               + ((lane >> 4) & 1) * 16);

    for (;;) {
        if (tid == 0) s_u = atomicAdd(&g_cnt, 4u);
        __syncthreads();
        const unsigned u = s_u;
        if (u >= NUNITS) break;
        const int m0 = (int)u * 32;

        const float* aptr[4];
#pragma unroll
        for (int i = 0; i < 4; ++i) {
            long gr = (long)m0 + rrow + i * 32 - B_DIM;
            if (gr < 0) gr = 0;
            if (gr > NROW - 1) gr = NROW - 1;
            aptr[i] = enc + (size_t)gr * H_DIM + c4;
        }

        float rowacc[4][2];
#pragma unroll
        for (int mt = 0; mt < 4; ++mt) { rowacc[mt][0] = 0.f; rowacc[mt][1] = 0.f; }

#pragma unroll 1
        for (int nt = 0; nt < 4; ++nt) {
            const int nbase = nt * 128;

            float cacc[4][4][4];
#pragma unroll
            for (int mt = 0; mt < 4; ++mt)
#pragma unroll
                for (int ntl = 0; ntl < 4; ++ntl)
#pragma unroll
                    for (int q = 0; q < 4; ++q) cacc[mt][ntl][q] = 0.f;

            float4 av[4];
            uint2 bh[4], bl[4];

            // prologue: stage 0 -> buf 0
#pragma unroll
            for (int i = 0; i < 4; ++i) av[i] = *(const float4*)(aptr[i]);
#pragma unroll
            for (int i = 0; i < 4; ++i) {
                const size_t o = (size_t)(nbase + rrow + i * 32) * H_DIM + c4;
                bh[i] = *(const uint2*)(g_Bh + o);
                bl[i] = *(const uint2*)(g_Bl + o);
            }
            {
                char* base = smem;
#pragma unroll
                for (int i = 0; i < 4; ++i) {
                    uint2 hi, lo; split4(av[i], hi, lo);
                    *(uint2*)(base + asts[i])              = hi;
                    *(uint2*)(base + TILE_B + asts[i])     = lo;
                    *(uint2*)(base + 2 * TILE_B + asts[i]) = bh[i];
                    *(uint2*)(base + 3 * TILE_B + asts[i]) = bl[i];
                }
            }
            __syncthreads();

#pragma unroll 1
            for (int st = 0; st < 16; ++st) {
                const int buf = st & 1;
                if (st < 15) {
                    const int kb = (st + 1) * 32;
#pragma unroll
                    for (int i = 0; i < 4; ++i) av[i] = *(const float4*)(aptr[i] + kb);
#pragma unroll
                    for (int i = 0; i < 4; ++i) {
                        const size_t o = (size_t)(nbase + rrow + i * 32) * H_DIM + kb + c4;
                        bh[i] = *(const uint2*)(g_Bh + o);
                        bl[i] = *(const uint2*)(g_Bl + o);
                    }
                }

                const uint32_t boffb = buf ? (uint32_t)BUF_B : 0u;
#pragma unroll
                for (int kk = 0; kk < 2; ++kk) {
                    const uint32_t koff = boffb + kk * 32;
                    uint32_t afh[4][4], afl[4][4];
                    uint32_t bfh[4][2], bfl[4][2];
#pragma unroll
                    for (int mt = 0; mt < 4; ++mt)
                        LDSM4(afh[mt][0], afh[mt][1], afh[mt][2], afh[mt][3],
                              a_addr[mt] + koff);
#pragma unroll
                    for (int p = 0; p < 2; ++p) {
                        uint32_t r0, r1, r2, r3;
                        LDSM4(r0, r1, r2, r3, b_addr[p] + koff);
                        bfh[2 * p][0] = r0;     bfh[2 * p][1] = r2;
                        bfh[2 * p + 1][0] = r1; bfh[2 * p + 1][1] = r3;
                    }
#pragma unroll
                    for (int mt = 0; mt < 4; ++mt)
#pragma unroll
                        for (int ntl = 0; ntl < 4; ++ntl)
                            MMA16816(cacc[mt][ntl], afh[mt], bfh[ntl][0], bfh[ntl][1]);
#pragma unroll
                    for (int mt = 0; mt < 4; ++mt)
                        LDSM4(afl[mt][0], afl[mt][1], afl[mt][2], afl[mt][3],
                              a_addr[mt] + koff + TILE_B);
#pragma unroll
                    for (int mt = 0; mt < 4; ++mt)
#pragma unroll
                        for (int ntl = 0; ntl < 4; ++ntl)
                            MMA16816(cacc[mt][ntl], afl[mt], bfh[ntl][0], bfh[ntl][1]);
#pragma unroll
                    for (int p = 0; p < 2; ++p) {
                        uint32_t r0, r1, r2, r3;
                        LDSM4(r0, r1, r2, r3, b_addr[p] + koff + TILE_B);
                        bfl[2 * p][0] = r0;     bfl[2 * p][1] = r2;
                        bfl[2 * p + 1][0] = r1; bfl[2 * p + 1][1] = r3;
                    }
#pragma unroll
                    for (int mt = 0; mt < 4; ++mt)
#pragma unroll
                        for (int ntl = 0; ntl < 4; ++ntl)
                            MMA16816(cacc[mt][ntl], afh[mt], bfl[ntl][0], bfl[ntl][1]);
                }

                if (st < 15) {
                    char* base = smem + (buf ^ 1) * BUF_B;
#pragma unroll
                    for (int i = 0; i < 4; ++i) {
                        uint2 hi, lo; split4(av[i], hi, lo);
                        *(uint2*)(base + asts[i])              = hi;
                        *(uint2*)(base + TILE_B + asts[i])     = lo;
                        *(uint2*)(base + 2 * TILE_B + asts[i]) = bh[i];
                        *(uint2*)(base + 3 * TILE_B + asts[i]) = bl[i];
                    }
                }
                __syncthreads();
            }

            // fused epilogue: rowacc += C .* (Enc .* hid), this n-tile
#pragma unroll
            for (int mt = 0; mt < 4; ++mt) {
#pragma unroll
                for (int j = 0; j < 2; ++j) {
                    int r = m0 + warp_m * 64 + mt * 16 + (lane >> 2) + j * 8;
                    if (r > NROW - 1) r = NROW - 1;
                    const float* er = enc + (size_t)r * H_DIM;
                    const float* hr = hid + (size_t)(r & 31) * H_DIM;
                    float acc = 0.f;
#pragma unroll
                    for (int ntl = 0; ntl < 4; ++ntl) {
                        const int col = nbase + warp_n * 32 + ntl * 8 + (lane & 3) * 2;
                        const float2 e = *(const float2*)(er + col);
                        const float2 h = *(const float2*)(hr + col);
                        acc = fmaf(cacc[mt][ntl][j * 2 + 0], e.x * h.x, acc);
                        acc = fmaf(cacc[mt][ntl][j * 2 + 1], e.y * h.y, acc);
                    }
                    rowacc[mt][j] += acc;
                }
            }
        }

        // reduce: quad lanes -> shared rows -> global (guarded)
        float* srow = (float*)smem;
        if (tid < 128) srow[tid] = 0.f;
        __syncthreads();
#pragma unroll
        for (int mt = 0; mt < 4; ++mt)
#pragma unroll
            for (int j = 0; j < 2; ++j) {
                float v = rowacc[mt][j];
                v += __shfl_xor_sync(0xffffffffu, v, 1);
                v += __shfl_xor_sync(0xffffffffu, v, 2);
                if ((lane & 3) == 0)
                    atomicAdd(&srow[warp_m * 64 + mt * 16 + (lane >> 2) + j * 8], v);
            }
        __syncthreads();
        if (tid < 128) {
            const int r = m0 + tid;
            if (r < NROW)
                logits[(r & 31) * S_LEN + (r >> 5)] = srow[tid];
        }
        __syncthreads();
    }
}

// ---------------- fp32 worker: persistent FFMA2 path, 128 threads ------------
#define FAST 36
__global__ __launch_bounds__(128, 1) void bilinear_fp32_ws(
    const float* __restrict__ enc, const float* __restrict__ hid,
    const float* __restrict__ Wm, float* __restrict__ logits)
{
    __shared__ float As[2][16][FAST];
    __shared__ float Bs[2][16][128];
    __shared__ unsigned s_u;

    const int tf  = threadIdx.x;         // 0..127
    const int frm = tf >> 4;             // 0..7 -> rows frm*4..+3
    const int fcn = tf & 15;             // cols fcn*8..+7
    const int farow = tf >> 2;           // 0..31  (A staging row)
    const int fac   = (tf & 3) * 4;      // A staging col
    const int wrow0 = tf >> 5;           // B staging rows wrow0 + 4j
    const int wc    = (tf & 31) * 4;     // B staging col

    for (;;) {
        if (tf == 0) s_u = atomicAdd(&g_cnt, 1u);
        __syncthreads();
        const unsigned u = s_u;
        if (u >= NUNITS) break;
        const int m0 = (int)u * 32;

        long fgr = (long)m0 + farow - B_DIM; if (fgr < 0) fgr = 0;
        const float* fap = enc + (size_t)fgr * H_DIM + fac;

        float frow[4] = {0.f, 0.f, 0.f, 0.f};

#pragma unroll 1
        for (int nt = 0; nt < 4; ++nt) {
            const int nbase = nt * 128;

            unsigned long long c[4][4];
#pragma unroll
            for (int i = 0; i < 4; ++i)
#pragma unroll
                for (int j = 0; j < 4; ++j) c[i][j] = 0ull;

            float4 fav;
            float4 fbv[4];

            // prologue stage 0 -> buf 0
            fav = *(const float4*)(fap);
#pragma unroll
            for (int j = 0; j < 4; ++j)
                fbv[j] = *(const float4*)(Wm + (size_t)(wrow0 + 4 * j) * H_DIM + nbase + wc);
            As[0][fac + 0][farow] = fav.x;
            As[0][fac + 1][farow] = fav.y;
            As[0][fac + 2][farow] = fav.z;
            As[0][fac + 3][farow] = fav.w;
#pragma unroll
            for (int j = 0; j < 4; ++j)
                *(float4*)&Bs[0][wrow0 + 4 * j][wc] = fbv[j];
            __syncthreads();

#pragma unroll 1
            for (int st = 0; st < 32; ++st) {
                const int buf = st & 1;
                if (st < 31) {
                    const int kb = (st + 1) * 16;
                    fav = *(const float4*)(fap + kb);
#pragma unroll
                    for (int j = 0; j < 4; ++j)
                        fbv[j] = *(const float4*)(Wm + (size_t)(kb + wrow0 + 4 * j) * H_DIM
                                                  + nbase + wc);
                }
#pragma unroll
                for (int kk = 0; kk < 16; ++kk) {
                    const float4 a = *(const float4*)&As[buf][kk][frm * 4];
                    const ulonglong2 b0 = *(const ulonglong2*)&Bs[buf][kk][fcn * 8];
                    const ulonglong2 b1 = *(const ulonglong2*)&Bs[buf][kk][fcn * 8 + 4];
                    const float aa[4] = {a.x, a.y, a.z, a.w};
#pragma unroll
                    for (int i = 0; i < 4; ++i) {
                        const unsigned long long ad = pk2(aa[i], aa[i]);
                        fma2(c[i][0], ad, b0.x);
                        fma2(c[i][1], ad, b0.y);
                        fma2(c[i][2], ad, b1.x);
                        fma2(c[i][3], ad, b1.y);
                    }
                }
                if (st < 31) {
                    const int nb = buf ^ 1;
                    As[nb][fac + 0][farow] = fav.x;
                    As[nb][fac + 1][farow] = fav.y;
                    As[nb][fac + 2][farow] = fav.z;
                    As[nb][fac + 3][farow] = fav.w;
#pragma unroll
                    for (int j = 0; j < 4; ++j)
                        *(float4*)&Bs[nb][wrow0 + 4 * j][wc] = fbv[j];
                }
                __syncthreads();
            }

            // epilogue this n-tile
#pragma unroll
            for (int i = 0; i < 4; ++i) {
                const int r = m0 + frm * 4 + i;
                const float* er = enc + (size_t)r * H_DIM + nbase + fcn * 8;
                const float* hr = hid + (size_t)(r & 31) * H_DIM + nbase + fcn * 8;
                const float4 e0 = *(const float4*)er;
                const float4 e1 = *(const float4*)(er + 4);
                const float4 h0 = *(const float4*)hr;
                const float4 h1 = *(const float4*)(hr + 4);
                const float2 c0 = up2(c[i][0]), c1 = up2(c[i][1]);
                const float2 c2 = up2(c[i][2]), c3 = up2(c[i][3]);
                float s = c0.x * e0.x * h0.x + c0.y * e0.y * h0.y
                        + c1.x * e0.z * h0.z + c1.y * e0.w * h0.w
                        + c2.x * e1.x * h1.x + c2.y * e1.y * h1.y
                        + c3.x * e1.z * h1.z + c3.y * e1.w * h1.w;
                s += __shfl_xor_sync(0xffffffffu, s, 8);
                s += __shfl_xor_sync(0xffffffffu, s, 4);
                s += __shfl_xor_sync(0xffffffffu, s, 2);
                s += __shfl_xor_sync(0xffffffffu, s, 1);
                frow[i] += s;   // valid on fcn==0 lanes
            }
        }

        if (fcn == 0) {
#pragma unroll
            for (int i = 0; i < 4; ++i) {
                const int r = m0 + frm * 4 + i;
                logits[(r & 31) * S_LEN + (r >> 5)] = frow[i];
            }
        }
        __syncthreads();
    }
}

// ---------------- kernel 2: affect term + s==0 fixup + softmax ----------------
__global__ __launch_bounds__(256) void softmax_finalize(
    const float* __restrict__ enc, const float* __restrict__ hid,
    const float* __restrict__ emb, const float* __restrict__ aff,
    float* __restrict__ out)
{
    const int b = blockIdx.x;
    const int tid = threadIdx.x;
    const int lane = tid & 31, wid = tid >> 5;
    __shared__ float red[8][4];
    __shared__ float fin[4];
    __shared__ float rmax[8];
    __shared__ float rsum[8];

    float a0 = 0.f, a1 = 0.f, a2 = 0.f, e0 = 0.f;
    for (int h = tid; h < H_DIM; h += 256) {
        const float hv = hid[b * H_DIM + h];
        a0 += hv * aff[h * 3 + 0];
        a1 += hv * aff[h * 3 + 1];
        a2 += hv * aff[h * 3 + 2];
        e0 += hv * enc[b * H_DIM + h];
    }
#pragma unroll
    for (int m = 16; m; m >>= 1) {
        a0 += __shfl_xor_sync(~0u, a0, m);
        a1 += __shfl_xor_sync(~0u, a1, m);
        a2 += __shfl_xor_sync(~0u, a2, m);
        e0 += __shfl_xor_sync(~0u, e0, m);
    }
    if (lane == 0) { red[wid][0] = a0; red[wid][1] = a1; red[wid][2] = a2; red[wid][3] = e0; }
    __syncthreads();
    if (tid < 4) {
        float s = 0.f;
        for (int w = 0; w < 8; ++w) s += red[w][tid];
        fin[tid] = s;
    }
    __syncthreads();
    const float A0 = fin[0], A1 = fin[1], A2 = fin[2], E0 = fin[3];

    float l[16];
    float mx = -INFINITY;
#pragma unroll
    for (int it = 0; it < 16; ++it) {
        const int s = tid + it * 256;
        float v = (s == 0) ? E0 : out[b * S_LEN + s];
        const float* ep = emb + ((size_t)s * B_DIM + b) * 3;
        v += A0 * ep[0] + A1 * ep[1] + A2 * ep[2];
        l[it] = v;
        mx = fmaxf(mx, v);
    }
#pragma unroll
    for (int m = 16; m; m >>= 1) mx = fmaxf(mx, __shfl_xor_sync(~0u, mx, m));
    if (lane == 0) rmax[wid] = mx;
    __syncthreads();
    if (tid == 0) {
        float m2 = rmax[0];
        for (int w = 1; w < 8; ++w) m2 = fmaxf(m2, rmax[w]);
        rmax[0] = m2;
    }
    __syncthreads();
    const float MX = rmax[0];

    float sum = 0.f;
#pragma unroll
    for (int it = 0; it < 16; ++it) { l[it] = expf(l[it] - MX); sum += l[it]; }
#pragma unroll
    for (int m = 16; m; m >>= 1) sum += __shfl_xor_sync(~0u, sum, m);
    if (lane == 0) rsum[wid] = sum;
    __syncthreads();
    if (tid == 0) {
        float s2 = 0.f;
        for (int w = 0; w < 8; ++w) s2 += rsum[w];
        rsum[0] = s2;
    }
    __syncthreads();
    const float inv = 1.0f / rsum[0];
#pragma unroll
    for (int it = 0; it < 16; ++it)
        out[b * S_LEN + tid + it * 256] = l[it] * inv;
}

// ---------------- launch: fork/join graph with two co-resident workers -------
extern "C" void kernel_launch(void* const* d_in, const int* in_sizes, int n_in,
                              void* d_out, int out_size) {
    const float *hid = nullptr, *enc = nullptr, *emb = nullptr, *Wm = nullptr, *aff = nullptr;
    for (int i = 0; i < n_in; ++i) {
        switch (in_sizes[i]) {
            case 16384:    hid = (const float*)d_in[i]; break;  // hidden [1,32,512]
            case 67108864: enc = (const float*)d_in[i]; break;  // encoder_outputs [4096,32,512]
            case 393216:   emb = (const float*)d_in[i]; break;  // embedding [4096,32,3]
            case 262144:   Wm  = (const float*)d_in[i]; break;  // bigram_matrix [512,512]
            case 1536:     aff = (const float*)d_in[i]; break;  // affect_matrix [512,3]
        }
    }
    float* out = (float*)d_out;  // [32,1,4096] fp32; logits scratch then softmax

    cudaFuncSetAttribute(bilinear_hmma_ws,
                         cudaFuncAttributeMaxDynamicSharedMemorySize, SMEM_TOTAL);

    // fork/join: fp32 worker on a second stream, tensor worker on the default
    // stream; both pull from g_cnt. Capturable (event fork/join only).
    cudaStream_t s2;
    cudaStreamCreateWithFlags(&s2, cudaStreamNonBlocking);
    cudaEvent_t e1, e2;
    cudaEventCreateWithFlags(&e1, cudaEventDisableTiming);
    cudaEventCreateWithFlags(&e2, cudaEventDisableTiming);

    split_w<<<(H_DIM * H_DIM) / 256, 256>>>(Wm);

    cudaEventRecord(e1, 0);
    cudaStreamWaitEvent(s2, e1, 0);
    bilinear_fp32_ws<<<148, 128, 0, s2>>>(enc, hid, Wm, out);
    bilinear_hmma_ws<<<148, 256, SMEM_TOTAL>>>(enc, hid, out);
    cudaEventRecord(e2, s2);
    cudaStreamWaitEvent(0, e2, 0);

    softmax_finalize<<<B_DIM, 256>>>(enc, hid, emb, aff, out);
}

// round 13
// speedup vs baseline: 2.3051x; 2.3051x over previous
#include <cuda_runtime.h>
#include <cuda_fp16.h>
#include <math.h>
#include <stdint.h>

#define S_LEN 4096
#define B_DIM 32
#define H_DIM 512
#define NROW  (S_LEN * B_DIM)   // 131072
#define NUNITS 4096             // 32-row work units

// ---------------- device scratch ----------------
__device__ __half g_Bh[H_DIM * H_DIM];   // fp16 hi(W[k][n]) transposed [n][k]
__device__ __half g_Bl[H_DIM * H_DIM];   // fp16 lo
__device__ unsigned g_cnt;               // shared work counter (reset by split_w)

__device__ __forceinline__ uint32_t smem_u32(const void* p) {
    uint32_t a;
    asm("{ .reg .u64 t; cvta.to.shared.u64 t, %1; cvt.u32.u64 %0, t; }" : "=r"(a) : "l"(p));
    return a;
}

#define LDSM4(r0, r1, r2, r3, addr) \
    asm volatile("ldmatrix.sync.aligned.m8n8.x4.shared.b16 {%0,%1,%2,%3}, [%4];" \
        : "=r"(r0), "=r"(r1), "=r"(r2), "=r"(r3) : "r"(addr))

#define MMA16816(c, a, b0, b1) \
    asm volatile("mma.sync.aligned.m16n8k16.row.col.f32.f16.f16.f32 " \
        "{%0,%1,%2,%3}, {%4,%5,%6,%7}, {%8,%9}, {%0,%1,%2,%3};" \
        : "+f"((c)[0]), "+f"((c)[1]), "+f"((c)[2]), "+f"((c)[3]) \
        : "r"((a)[0]), "r"((a)[1]), "r"((a)[2]), "r"((a)[3]), "r"(b0), "r"(b1))

// packed fp32x2 helpers (FFMA2 path)
__device__ __forceinline__ unsigned long long pk2(float x, float y) {
    unsigned long long r;
    asm("mov.b64 %0, {%1, %2};" : "=l"(r) : "f"(x), "f"(y));
    return r;
}
__device__ __forceinline__ void fma2(unsigned long long &d, unsigned long long a, unsigned long long b) {
    asm("fma.rn.f32x2 %0, %1, %2, %0;" : "+l"(d) : "l"(a), "l"(b));
}
__device__ __forceinline__ float2 up2(unsigned long long v) {
    float2 r;
    asm("mov.b64 {%0, %1}, %2;" : "=f"(r.x), "=f"(r.y) : "l"(v));
    return r;
}

__device__ __forceinline__ void split4(float4 v, uint2& hi, uint2& lo) {
    __half2 h01 = __floats2half2_rn(v.x, v.y);
    __half2 h23 = __floats2half2_rn(v.z, v.w);
    float2 f01 = __half22float2(h01);
    float2 f23 = __half22float2(h23);
    __half2 l01 = __floats2half2_rn(v.x - f01.x, v.y - f01.y);
    __half2 l23 = __floats2half2_rn(v.z - f23.x, v.w - f23.y);
    hi.x = *(uint32_t*)&h01; hi.y = *(uint32_t*)&h23;
    lo.x = *(uint32_t*)&l01; lo.y = *(uint32_t*)&l23;
}

// ---------------- kernel 0: split W (transposed) + counter reset -------------
__global__ __launch_bounds__(256) void split_w(const float* __restrict__ Wm) {
    if (blockIdx.x == 0 && threadIdx.x == 0) g_cnt = 0;
    int idx = blockIdx.x * 256 + threadIdx.x;   // 0 .. 262143
    int k = idx >> 9, n = idx & 511;
    float v = Wm[idx];
    __half hi = __float2half_rn(v);
    g_Bh[n * H_DIM + k] = hi;
    g_Bl[n * H_DIM + k] = __float2half_rn(v - __half2float(hi));
}

// ---------------- SMEM geometry ----------------
// tensor path: per buffer 4 tiles (A_hi, A_lo, B_hi, B_lo), 128 rows x 40 halfs
#define TSTRIDE_B 80
#define TILE_B    (128 * TSTRIDE_B)   // 10240
#define BUF_B     (4 * TILE_B)        // 40960
#define SMEM_TOTAL (2 * BUF_B)        // 81920
// fp32 path reuses the same dynamic buffer:
//   As[2][16][132] floats (16896 B) then Bs[2][16][128] floats (16384 B)
#define F_AST 132
#define F_BS_OFF 16896

// ---------------- combined GEMM-bilinear kernel (CTA-specialized) ------------
// rows r = s*32+b; A[m] = Enc[r-32] (rows r<32 garbage, fixed by softmax kernel)
// logit[r] = sum_n C[r,n] * Enc[r,n] * hid[b,n],  C = Enc[r-32] @ W
__global__ __launch_bounds__(256, 2) void bilinear_combo(
    const float* __restrict__ enc, const float* __restrict__ hid,
    const float* __restrict__ Wm, float* __restrict__ logits)
{
    extern __shared__ char smem[];
    __shared__ unsigned s_u;
    const int tid = threadIdx.x;

    if (blockIdx.x < 148) {
        // ==================== tensor path: 3xFP16 HMMA (R6 body) ====================
        const uint32_t sb = smem_u32(smem);
        const int lane = tid & 31, wid = tid >> 5;
        const int warp_m = wid >> 2;
        const int warp_n = wid & 3;

        const int rrow = tid >> 3;
        const int c4   = (tid & 7) * 4;
        uint32_t asts[4];
#pragma unroll
        for (int i = 0; i < 4; ++i)
            asts[i] = (uint32_t)((rrow + i * 32) * TSTRIDE_B + c4 * 2);

        uint32_t a_addr[4];
#pragma unroll
        for (int mt = 0; mt < 4; ++mt)
            a_addr[mt] = sb + (uint32_t)((warp_m * 64 + mt * 16 + (lane & 15)) * TSTRIDE_B
                                         + ((lane >> 4) & 1) * 16);
        uint32_t b_addr[2];
#pragma unroll
        for (int p = 0; p < 2; ++p)
            b_addr[p] = sb + 2 * TILE_B +
                        (uint32_t)((warp_n * 32 + p * 16 + (lane & 15)) * TSTRIDE_B
                                   + ((lane >> 4) & 1) * 16);

        for (;;) {
            if (tid == 0) s_u = atomicAdd(&g_cnt, 4u);
            __syncthreads();
            const unsigned u = s_u;
            if (u >= NUNITS) break;
            const int m0 = (int)u * 32;

            const float* aptr[4];
#pragma unroll
            for (int i = 0; i < 4; ++i) {
                long gr = (long)m0 + rrow + i * 32 - B_DIM;
                if (gr < 0) gr = 0;
                aptr[i] = enc + (size_t)gr * H_DIM + c4;
            }

            float rowacc[4][2];
#pragma unroll
            for (int mt = 0; mt < 4; ++mt) { rowacc[mt][0] = 0.f; rowacc[mt][1] = 0.f; }

#pragma unroll 1
            for (int nt = 0; nt < 4; ++nt) {
                const int nbase = nt * 128;

                float cacc[4][4][4];
#pragma unroll
                for (int mt = 0; mt < 4; ++mt)
#pragma unroll
                    for (int ntl = 0; ntl < 4; ++ntl)
#pragma unroll
                        for (int q = 0; q < 4; ++q) cacc[mt][ntl][q] = 0.f;

                float4 av[4];
                uint2 bh[4], bl[4];

#pragma unroll
                for (int i = 0; i < 4; ++i) av[i] = *(const float4*)(aptr[i]);
#pragma unroll
                for (int i = 0; i < 4; ++i) {
                    const size_t o = (size_t)(nbase + rrow + i * 32) * H_DIM + c4;
                    bh[i] = *(const uint2*)(g_Bh + o);
                    bl[i] = *(const uint2*)(g_Bl + o);
                }
                {
                    char* base = smem;
#pragma unroll
                    for (int i = 0; i < 4; ++i) {
                        uint2 hi, lo; split4(av[i], hi, lo);
                        *(uint2*)(base + asts[i])              = hi;
                        *(uint2*)(base + TILE_B + asts[i])     = lo;
                        *(uint2*)(base + 2 * TILE_B + asts[i]) = bh[i];
                        *(uint2*)(base + 3 * TILE_B + asts[i]) = bl[i];
                    }
                }
                __syncthreads();

#pragma unroll 1
                for (int st = 0; st < 16; ++st) {
                    const int buf = st & 1;
                    if (st < 15) {
                        const int kb = (st + 1) * 32;
#pragma unroll
                        for (int i = 0; i < 4; ++i) av[i] = *(const float4*)(aptr[i] + kb);
#pragma unroll
                        for (int i = 0; i < 4; ++i) {
                            const size_t o = (size_t)(nbase + rrow + i * 32) * H_DIM + kb + c4;
                            bh[i] = *(const uint2*)(g_Bh + o);
                            bl[i] = *(const uint2*)(g_Bl + o);
                        }
                    }

                    const uint32_t boffb = buf ? (uint32_t)BUF_B : 0u;
#pragma unroll
                    for (int kk = 0; kk < 2; ++kk) {
                        const uint32_t koff = boffb + kk * 32;
                        uint32_t afh[4][4], afl[4][4];
                        uint32_t bfh[4][2], bfl[4][2];
#pragma unroll
                        for (int mt = 0; mt < 4; ++mt)
                            LDSM4(afh[mt][0], afh[mt][1], afh[mt][2], afh[mt][3],
                                  a_addr[mt] + koff);
#pragma unroll
                        for (int p = 0; p < 2; ++p) {
                            uint32_t r0, r1, r2, r3;
                            LDSM4(r0, r1, r2, r3, b_addr[p] + koff);
                            bfh[2 * p][0] = r0;     bfh[2 * p][1] = r2;
                            bfh[2 * p + 1][0] = r1; bfh[2 * p + 1][1] = r3;
                        }
#pragma unroll
                        for (int mt = 0; mt < 4; ++mt)
#pragma unroll
                            for (int ntl = 0; ntl < 4; ++ntl)
                                MMA16816(cacc[mt][ntl], afh[mt], bfh[ntl][0], bfh[ntl][1]);
#pragma unroll
                        for (int mt = 0; mt < 4; ++mt)
                            LDSM4(afl[mt][0], afl[mt][1], afl[mt][2], afl[mt][3],
                                  a_addr[mt] + koff + TILE_B);
#pragma unroll
                        for (int mt = 0; mt < 4; ++mt)
#pragma unroll
                            for (int ntl = 0; ntl < 4; ++ntl)
                                MMA16816(cacc[mt][ntl], afl[mt], bfh[ntl][0], bfh[ntl][1]);
#pragma unroll
                        for (int p = 0; p < 2; ++p) {
                            uint32_t r0, r1, r2, r3;
                            LDSM4(r0, r1, r2, r3, b_addr[p] + koff + TILE_B);
                            bfl[2 * p][0] = r0;     bfl[2 * p][1] = r2;
                            bfl[2 * p + 1][0] = r1; bfl[2 * p + 1][1] = r3;
                        }
#pragma unroll
                        for (int mt = 0; mt < 4; ++mt)
#pragma unroll
                            for (int ntl = 0; ntl < 4; ++ntl)
                                MMA16816(cacc[mt][ntl], afh[mt], bfl[ntl][0], bfl[ntl][1]);
                    }

                    if (st < 15) {
                        char* base = smem + (buf ^ 1) * BUF_B;
#pragma unroll
                        for (int i = 0; i < 4; ++i) {
                            uint2 hi, lo; split4(av[i], hi, lo);
                            *(uint2*)(base + asts[i])              = hi;
                            *(uint2*)(base + TILE_B + asts[i])     = lo;
                            *(uint2*)(base + 2 * TILE_B + asts[i]) = bh[i];
                            *(uint2*)(base + 3 * TILE_B + asts[i]) = bl[i];
                        }
                    }
                    __syncthreads();
                }

                // fused epilogue
#pragma unroll
                for (int mt = 0; mt < 4; ++mt) {
#pragma unroll
                    for (int j = 0; j < 2; ++j) {
                        const int r = m0 + warp_m * 64 + mt * 16 + (lane >> 2) + j * 8;
                        const float* er = enc + (size_t)r * H_DIM;
                        const float* hr = hid + (size_t)(r & 31) * H_DIM;
                        float acc = 0.f;
#pragma unroll
                        for (int ntl = 0; ntl < 4; ++ntl) {
                            const int col = nbase + warp_n * 32 + ntl * 8 + (lane & 3) * 2;
                            const float2 e = *(const float2*)(er + col);
                            const float2 h = *(const float2*)(hr + col);
                            acc = fmaf(cacc[mt][ntl][j * 2 + 0], e.x * h.x, acc);
                            acc = fmaf(cacc[mt][ntl][j * 2 + 1], e.y * h.y, acc);
                        }
                        rowacc[mt][j] += acc;
                    }
                }
            }

            // reduce: quad lanes -> shared rows -> global
            float* srow = (float*)smem;
            if (tid < 128) srow[tid] = 0.f;
            __syncthreads();
#pragma unroll
            for (int mt = 0; mt < 4; ++mt)
#pragma unroll
                for (int j = 0; j < 2; ++j) {
                    float v = rowacc[mt][j];
                    v += __shfl_xor_sync(0xffffffffu, v, 1);
                    v += __shfl_xor_sync(0xffffffffu, v, 2);
                    if ((lane & 3) == 0)
                        atomicAdd(&srow[warp_m * 64 + mt * 16 + (lane >> 2) + j * 8], v);
                }
            __syncthreads();
            if (tid < 128) {
                const int r = m0 + tid;
                logits[(r & 31) * S_LEN + (r >> 5)] = srow[tid];
            }
            __syncthreads();
        }
    } else {
        // ==================== fp32 path: FFMA2 (R3 body) ====================
        float* As = (float*)smem;                  // [2][16][132]
        float* Bs = (float*)(smem + F_BS_OFF);     // [2][16][128]

        const int rm = tid >> 4;     // 0..15  (row group of 8)
        const int cn = tid & 15;     // 0..15  (col group of 8)
        const int aRow0 = tid >> 2;
        const int aRow1 = aRow0 + 64;
        const int aC    = (tid & 3) * 4;
        const int bRow = tid >> 5;
        const int bCol = (tid & 31) * 4;

        for (;;) {
            if (tid == 0) s_u = atomicAdd(&g_cnt, 4u);
            __syncthreads();
            const unsigned u = s_u;
            if (u >= NUNITS) break;
            const int m0 = (int)u * 32;

            long xr0 = (long)m0 + aRow0 - B_DIM; if (xr0 < 0) xr0 = 0;
            long xr1 = (long)m0 + aRow1 - B_DIM; if (xr1 < 0) xr1 = 0;

            float rowacc[8];
#pragma unroll
            for (int i = 0; i < 8; ++i) rowacc[i] = 0.f;

#pragma unroll 1
            for (int nt = 0; nt < 4; ++nt) {
                const int nbase = nt * 128;
                unsigned long long c[8][4];
#pragma unroll
                for (int i = 0; i < 8; ++i)
#pragma unroll
                    for (int j = 0; j < 4; ++j) c[i][j] = 0ull;

                float4 av0, av1, bv0, bv1;
                av0 = *(const float4*)(enc + xr0 * H_DIM + aC);
                av1 = *(const float4*)(enc + xr1 * H_DIM + aC);
                bv0 = *(const float4*)(Wm + (size_t)bRow * H_DIM + nbase + bCol);
                bv1 = *(const float4*)(Wm + (size_t)(bRow + 8) * H_DIM + nbase + bCol);
                As[(aC+0) * F_AST + aRow0] = av0.x; As[(aC+1) * F_AST + aRow0] = av0.y;
                As[(aC+2) * F_AST + aRow0] = av0.z; As[(aC+3) * F_AST + aRow0] = av0.w;
                As[(aC+0) * F_AST + aRow1] = av1.x; As[(aC+1) * F_AST + aRow1] = av1.y;
                As[(aC+2) * F_AST + aRow1] = av1.z; As[(aC+3) * F_AST + aRow1] = av1.w;
                *(float4*)&Bs[bRow * 128 + bCol]       = bv0;
                *(float4*)&Bs[(bRow + 8) * 128 + bCol] = bv1;
                __syncthreads();

#pragma unroll 1
                for (int st = 0; st < 32; ++st) {
                    const int buf = st & 1;
                    if (st < 31) {
                        const int kb = (st + 1) * 16;
                        av0 = *(const float4*)(enc + xr0 * H_DIM + kb + aC);
                        av1 = *(const float4*)(enc + xr1 * H_DIM + kb + aC);
                        bv0 = *(const float4*)(Wm + (size_t)(kb + bRow) * H_DIM + nbase + bCol);
                        bv1 = *(const float4*)(Wm + (size_t)(kb + bRow + 8) * H_DIM + nbase + bCol);
                    }
                    const float* Asb = As + buf * 16 * F_AST;
                    const float* Bsb = Bs + buf * 16 * 128;
#pragma unroll
                    for (int kk = 0; kk < 16; ++kk) {
                        const float4 a0 = *(const float4*)(Asb + kk * F_AST + rm * 8);
                        const float4 a1 = *(const float4*)(Asb + kk * F_AST + rm * 8 + 4);
                        const ulonglong2 b0 = *(const ulonglong2*)(Bsb + kk * 128 + cn * 8);
                        const ulonglong2 b1 = *(const ulonglong2*)(Bsb + kk * 128 + cn * 8 + 4);
                        const float a_[8] = {a0.x, a0.y, a0.z, a0.w, a1.x, a1.y, a1.z, a1.w};
#pragma unroll
                        for (int i = 0; i < 8; ++i) {
                            const unsigned long long ad = pk2(a_[i], a_[i]);
                            fma2(c[i][0], ad, b0.x);
                            fma2(c[i][1], ad, b0.y);
                            fma2(c[i][2], ad, b1.x);
                            fma2(c[i][3], ad, b1.y);
                        }
                    }
                    if (st < 31) {
                        const int nb = buf ^ 1;
                        float* Asn = As + nb * 16 * F_AST;
                        float* Bsn = Bs + nb * 16 * 128;
                        Asn[(aC+0) * F_AST + aRow0] = av0.x; Asn[(aC+1) * F_AST + aRow0] = av0.y;
                        Asn[(aC+2) * F_AST + aRow0] = av0.z; Asn[(aC+3) * F_AST + aRow0] = av0.w;
                        Asn[(aC+0) * F_AST + aRow1] = av1.x; Asn[(aC+1) * F_AST + aRow1] = av1.y;
                        Asn[(aC+2) * F_AST + aRow1] = av1.z; Asn[(aC+3) * F_AST + aRow1] = av1.w;
                        *(float4*)&Bsn[bRow * 128 + bCol]       = bv0;
                        *(float4*)&Bsn[(bRow + 8) * 128 + bCol] = bv1;
                    }
                    __syncthreads();
                }

                // epilogue this n-tile
#pragma unroll
                for (int i = 0; i < 8; ++i) {
                    const long rg = m0 + rm * 8 + i;
                    const float* er = enc + rg * H_DIM + nbase + cn * 8;
                    const float* hr = hid + (size_t)(rg & 31) * H_DIM + nbase + cn * 8;
                    const float4 e0 = *(const float4*)er;
                    const float4 e1 = *(const float4*)(er + 4);
                    const float4 h0 = *(const float4*)hr;
                    const float4 h1 = *(const float4*)(hr + 4);
                    const float2 c0 = up2(c[i][0]), c1 = up2(c[i][1]);
                    const float2 c2 = up2(c[i][2]), c3 = up2(c[i][3]);
                    float s = c0.x * e0.x * h0.x + c0.y * e0.y * h0.y
                            + c1.x * e0.z * h0.z + c1.y * e0.w * h0.w
                            + c2.x * e1.x * h1.x + c2.y * e1.y * h1.y
                            + c3.x * e1.z * h1.z + c3.y * e1.w * h1.w;
                    s += __shfl_xor_sync(0xffffffffu, s, 8);
                    s += __shfl_xor_sync(0xffffffffu, s, 4);
                    s += __shfl_xor_sync(0xffffffffu, s, 2);
                    s += __shfl_xor_sync(0xffffffffu, s, 1);
                    rowacc[i] += s;   // valid on cn==0 lanes
                }
                __syncthreads();
            }

            if (cn == 0) {
#pragma unroll
                for (int i = 0; i < 8; ++i) {
                    const int rg = m0 + rm * 8 + i;
                    logits[(rg & 31) * S_LEN + (rg >> 5)] = rowacc[i];
                }
            }
            __syncthreads();
        }
    }
}

// ---------------- kernel 2: affect term + s==0 fixup + softmax ----------------
__global__ __launch_bounds__(256) void softmax_finalize(
    const float* __restrict__ enc, const float* __restrict__ hid,
    const float* __restrict__ emb, const float* __restrict__ aff,
    float* __restrict__ out)
{
    const int b = blockIdx.x;
    const int tid = threadIdx.x;
    const int lane = tid & 31, wid = tid >> 5;
    __shared__ float red[8][4];
    __shared__ float fin[4];
    __shared__ float rmax[8];
    __shared__ float rsum[8];

    float a0 = 0.f, a1 = 0.f, a2 = 0.f, e0 = 0.f;
    for (int h = tid; h < H_DIM; h += 256) {
        const float hv = hid[b * H_DIM + h];
        a0 += hv * aff[h * 3 + 0];
        a1 += hv * aff[h * 3 + 1];
        a2 += hv * aff[h * 3 + 2];
        e0 += hv * enc[b * H_DIM + h];
    }
#pragma unroll
    for (int m = 16; m; m >>= 1) {
        a0 += __shfl_xor_sync(~0u, a0, m);
        a1 += __shfl_xor_sync(~0u, a1, m);
        a2 += __shfl_xor_sync(~0u, a2, m);
        e0 += __shfl_xor_sync(~0u, e0, m);
    }
    if (lane == 0) { red[wid][0] = a0; red[wid][1] = a1; red[wid][2] = a2; red[wid][3] = e0; }
    __syncthreads();
    if (tid < 4) {
        float s = 0.f;
        for (int w = 0; w < 8; ++w) s += red[w][tid];
        fin[tid] = s;
    }
    __syncthreads();
    const float A0 = fin[0], A1 = fin[1], A2 = fin[2], E0 = fin[3];

    float l[16];
    float mx = -INFINITY;
#pragma unroll
    for (int it = 0; it < 16; ++it) {
        const int s = tid + it * 256;
        float v = (s == 0) ? E0 : out[b * S_LEN + s];
        const float* ep = emb + ((size_t)s * B_DIM + b) * 3;
        v += A0 * ep[0] + A1 * ep[1] + A2 * ep[2];
        l[it] = v;
        mx = fmaxf(mx, v);
    }
#pragma unroll
    for (int m = 16; m; m >>= 1) mx = fmaxf(mx, __shfl_xor_sync(~0u, mx, m));
    if (lane == 0) rmax[wid] = mx;
    __syncthreads();
    if (tid == 0) {
        float m2 = rmax[0];
        for (int w = 1; w < 8; ++w) m2 = fmaxf(m2, rmax[w]);
        rmax[0] = m2;
    }
    __syncthreads();
    const float MX = rmax[0];

    float sum = 0.f;
#pragma unroll
    for (int it = 0; it < 16; ++it) { l[it] = expf(l[it] - MX); sum += l[it]; }
#pragma unroll
    for (int m = 16; m; m >>= 1) sum += __shfl_xor_sync(~0u, sum, m);
    if (lane == 0) rsum[wid] = sum;
    __syncthreads();
    if (tid == 0) {
        float s2 = 0.f;
        for (int w = 0; w < 8; ++w) s2 += rsum[w];
        rsum[0] = s2;
    }
    __syncthreads();
    const float inv = 1.0f / rsum[0];
#pragma unroll
    for (int it = 0; it < 16; ++it)
        out[b * S_LEN + tid + it * 256] = l[it] * inv;
}

// ---------------- launch ----------------
extern "C" void kernel_launch(void* const* d_in, const int* in_sizes, int n_in,
                              void* d_out, int out_size) {
    const float *hid = nullptr, *enc = nullptr, *emb = nullptr, *Wm = nullptr, *aff = nullptr;
    for (int i = 0; i < n_in; ++i) {
        switch (in_sizes[i]) {
            case 16384:    hid = (const float*)d_in[i]; break;  // hidden [1,32,512]
            case 67108864: enc = (const float*)d_in[i]; break;  // encoder_outputs [4096,32,512]
            case 393216:   emb = (const float*)d_in[i]; break;  // embedding [4096,32,3]
            case 262144:   Wm  = (const float*)d_in[i]; break;  // bigram_matrix [512,512]
            case 1536:     aff = (const float*)d_in[i]; break;  // affect_matrix [512,3]
        }
    }
    float* out = (float*)d_out;  // [32,1,4096] fp32; logits scratch then softmax

    cudaFuncSetAttribute(bilinear_combo,
                         cudaFuncAttributeMaxDynamicSharedMemorySize, SMEM_TOTAL);

    split_w<<<(H_DIM * H_DIM) / 256, 256>>>(Wm);
    bilinear_combo<<<296, 256, SMEM_TOTAL>>>(enc, hid, Wm, out);
    softmax_finalize<<<B_DIM, 256>>>(enc, hid, emb, aff, out);
}

// round 14
// speedup vs baseline: 3.6505x; 1.5837x over previous
#include <cuda_runtime.h>
#include <cuda_fp16.h>
#include <math.h>
#include <stdint.h>

#define S_LEN 4096
#define B_DIM 32
#define H_DIM 512
#define NROW  (S_LEN * B_DIM)   // 131072

#define CROSS_SCALE 4096.0f
#define INV_CROSS   2.44140625e-4f   // 2^-12

// ---------------- device scratch: transposed fp16 split of bigram matrix ----
// g_Bh[n*512+k] = hi(W[k][n]);  g_Bl = (W - hi(W)) * 4096 in fp16
__device__ __half g_Bh[H_DIM * H_DIM];
__device__ __half g_Bl[H_DIM * H_DIM];

__device__ __forceinline__ uint32_t smem_u32(const void* p) {
    uint32_t a;
    asm("{ .reg .u64 t; cvta.to.shared.u64 t, %1; cvt.u32.u64 %0, t; }" : "=r"(a) : "l"(p));
    return a;
}

#define LDSM4(r0, r1, r2, r3, addr) \
    asm volatile("ldmatrix.sync.aligned.m8n8.x4.shared.b16 {%0,%1,%2,%3}, [%4];" \
        : "=r"(r0), "=r"(r1), "=r"(r2), "=r"(r3) : "r"(addr))

// f32-accumulate HMMA (hi*hi term)
#define MMA16816(c, a, b0, b1) \
    asm volatile("mma.sync.aligned.m16n8k16.row.col.f32.f16.f16.f32 " \
        "{%0,%1,%2,%3}, {%4,%5,%6,%7}, {%8,%9}, {%0,%1,%2,%3};" \
        : "+f"((c)[0]), "+f"((c)[1]), "+f"((c)[2]), "+f"((c)[3]) \
        : "r"((a)[0]), "r"((a)[1]), "r"((a)[2]), "r"((a)[3]), "r"(b0), "r"(b1))

// f16-accumulate HMMA (cross terms, 2^12-scaled operands)
#define MMA16816H(c, a, b0, b1) \
    asm volatile("mma.sync.aligned.m16n8k16.row.col.f16.f16.f16.f16 " \
        "{%0,%1}, {%2,%3,%4,%5}, {%6,%7}, {%0,%1};" \
        : "+r"((c)[0]), "+r"((c)[1]) \
        : "r"((a)[0]), "r"((a)[1]), "r"((a)[2]), "r"((a)[3]), "r"(b0), "r"(b1))

// ---------------- kernel 0: split W (transposed), lo scaled by 2^12 ----------
__global__ __launch_bounds__(256) void split_w(const float* __restrict__ Wm) {
    int idx = blockIdx.x * 256 + threadIdx.x;   // 0 .. 262143
    int k = idx >> 9, n = idx & 511;
    float v = Wm[idx];
    __half hi = __float2half_rn(v);
    float lof = (v - __half2float(hi)) * CROSS_SCALE;
    g_Bh[n * H_DIM + k] = hi;
    g_Bl[n * H_DIM + k] = __float2half_rn(lof);
}

// split with 2^12-scaled lo plane
__device__ __forceinline__ void split4s(float4 v, uint2& hi, uint2& lo) {
    __half2 h01 = __floats2half2_rn(v.x, v.y);
    __half2 h23 = __floats2half2_rn(v.z, v.w);
    float2 f01 = __half22float2(h01);
    float2 f23 = __half22float2(h23);
    __half2 l01 = __floats2half2_rn((v.x - f01.x) * CROSS_SCALE, (v.y - f01.y) * CROSS_SCALE);
    __half2 l23 = __floats2half2_rn((v.z - f23.x) * CROSS_SCALE, (v.w - f23.y) * CROSS_SCALE);
    hi.x = *(uint32_t*)&h01; hi.y = *(uint32_t*)&h23;
    lo.x = *(uint32_t*)&l01; lo.y = *(uint32_t*)&l23;
}

// ---------------- kernel 1: fp16 GEMM-bilinear -> logits (R6 skeleton) -------
// rows r = s*32+b; A[m] = Enc[r-32] (rows r<32 garbage, fixed by kernel 2)
// C = ah@wh (f32 acc) + 2^-12 * (al'@wh + ah@wl') (f16 acc, operands 2^12-scaled)
// logit[r] = sum_n C[r,n] * Enc[r,n] * hid[b,n]
//
// SMEM: per buffer 4 tiles (A_hi, A_lo', B_hi, B_lo'), 128 rows x 40 halfs (80B)
#define TSTRIDE_B 80
#define TILE_B    (128 * TSTRIDE_B)   // 10240
#define BUF_B     (4 * TILE_B)        // 40960
#define SMEM_TOTAL (2 * BUF_B)        // 81920

__global__ __launch_bounds__(256, 1) void bilinear_hmma(
    const float* __restrict__ enc, const float* __restrict__ hid,
    float* __restrict__ logits)
{
    extern __shared__ char smem[];
    const uint32_t sb = smem_u32(smem);
    const int tid = threadIdx.x;
    const int lane = tid & 31, wid = tid >> 5;
    const int warp_m = wid >> 2;     // 0..1 : m offset 64*warp_m
    const int warp_n = wid & 3;      // 0..3 : n offset 32*warp_n
    const int m0 = blockIdx.x * 128;

    // ---- fill mapping: slot = tid + i*256; row = slot>>3; c4 = (slot&7)*4 ----
    const int rrow = tid >> 3;           // 0..31
    const int c4   = (tid & 7) * 4;      // 0,4,..,28
    const float* aptr[4];
    uint32_t asts[4];
#pragma unroll
    for (int i = 0; i < 4; ++i) {
        const int row = rrow + i * 32;
        long gr = (long)m0 + row - B_DIM; if (gr < 0) gr = 0;
        aptr[i] = enc + (size_t)gr * H_DIM + c4;
        asts[i] = (uint32_t)(row * TSTRIDE_B + c4 * 2);
    }

    // ---- ldmatrix addresses ----
    uint32_t a_addr[4];
#pragma unroll
    for (int mt = 0; mt < 4; ++mt)
        a_addr[mt] = sb + (uint32_t)((warp_m * 64 + mt * 16 + (lane & 15)) * TSTRIDE_B
                                     + ((lane >> 4) & 1) * 16);
    uint32_t b_addr[2];
#pragma unroll
    for (int p = 0; p < 2; ++p)
        b_addr[p] = sb + 2 * TILE_B + (uint32_t)((warp_n * 32 + p * 16 + (lane & 15)) * TSTRIDE_B
                                                 + ((lane >> 4) & 1) * 16);

    float rowacc[4][2];
#pragma unroll
    for (int mt = 0; mt < 4; ++mt) { rowacc[mt][0] = 0.f; rowacc[mt][1] = 0.f; }

#pragma unroll 1
    for (int nt = 0; nt < 4; ++nt) {
        const int nbase = nt * 128;

        float    chh[4][4][4];   // hi*hi, f32 accumulators
        uint32_t ccr[4][4][2];   // cross, f16x2 accumulators (2^12 scale)
#pragma unroll
        for (int mt = 0; mt < 4; ++mt)
#pragma unroll
            for (int ntl = 0; ntl < 4; ++ntl) {
#pragma unroll
                for (int q = 0; q < 4; ++q) chh[mt][ntl][q] = 0.f;
                ccr[mt][ntl][0] = 0u; ccr[mt][ntl][1] = 0u;
            }

        float4 av[4];
        uint2 bh[4], bl[4];

        // ---- prologue: LDG + STS stage 0 -> buf 0 ----
#pragma unroll
        for (int i = 0; i < 4; ++i) av[i] = *(const float4*)(aptr[i]);
#pragma unroll
        for (int i = 0; i < 4; ++i) {
            const size_t o = (size_t)(nbase + rrow + i * 32) * H_DIM + c4;
            bh[i] = *(const uint2*)(g_Bh + o);
            bl[i] = *(const uint2*)(g_Bl + o);
        }
        {
            char* base = smem;
#pragma unroll
            for (int i = 0; i < 4; ++i) {
                uint2 hi, lo; split4s(av[i], hi, lo);
                *(uint2*)(base + asts[i])              = hi;
                *(uint2*)(base + TILE_B + asts[i])     = lo;
                *(uint2*)(base + 2 * TILE_B + asts[i]) = bh[i];
                *(uint2*)(base + 3 * TILE_B + asts[i]) = bl[i];
            }
        }
        __syncthreads();

#pragma unroll 1
        for (int st = 0; st < 16; ++st) {
            const int buf = st & 1;
            if (st < 15) {
                const int kb = (st + 1) * 32;
#pragma unroll
                for (int i = 0; i < 4; ++i) av[i] = *(const float4*)(aptr[i] + kb);
#pragma unroll
                for (int i = 0; i < 4; ++i) {
                    const size_t o = (size_t)(nbase + rrow + i * 32) * H_DIM + kb + c4;
                    bh[i] = *(const uint2*)(g_Bh + o);
                    bl[i] = *(const uint2*)(g_Bl + o);
                }
            }

            const uint32_t boff = buf ? (uint32_t)BUF_B : 0u;
#pragma unroll
            for (int kk = 0; kk < 2; ++kk) {
                const uint32_t koff = boff + kk * 32;   // 16 halfs = 32B per k16
                uint32_t afh[4][4], afl[4][4];
                uint32_t bfh[4][2], bfl[4][2];
                // A_hi
#pragma unroll
                for (int mt = 0; mt < 4; ++mt)
                    LDSM4(afh[mt][0], afh[mt][1], afh[mt][2], afh[mt][3], a_addr[mt] + koff);
                // B_hi
#pragma unroll
                for (int p = 0; p < 2; ++p) {
                    uint32_t r0, r1, r2, r3;
                    LDSM4(r0, r1, r2, r3, b_addr[p] + koff);
                    bfh[2 * p][0] = r0;     bfh[2 * p][1] = r2;
                    bfh[2 * p + 1][0] = r1; bfh[2 * p + 1][1] = r3;
                }
                // hi * hi  (f32 acc)
#pragma unroll
                for (int mt = 0; mt < 4; ++mt)
#pragma unroll
                    for (int ntl = 0; ntl < 4; ++ntl)
                        MMA16816(chh[mt][ntl], afh[mt], bfh[ntl][0], bfh[ntl][1]);
                // lo' * hi  (f16 acc)
#pragma unroll
                for (int mt = 0; mt < 4; ++mt)
                    LDSM4(afl[mt][0], afl[mt][1], afl[mt][2], afl[mt][3],
                          a_addr[mt] + koff + TILE_B);
#pragma unroll
                for (int mt = 0; mt < 4; ++mt)
#pragma unroll
                    for (int ntl = 0; ntl < 4; ++ntl)
                        MMA16816H(ccr[mt][ntl], afl[mt], bfh[ntl][0], bfh[ntl][1]);
                // hi * lo'  (f16 acc)
#pragma unroll
                for (int p = 0; p < 2; ++p) {
                    uint32_t r0, r1, r2, r3;
                    LDSM4(r0, r1, r2, r3, b_addr[p] + koff + TILE_B);
                    bfl[2 * p][0] = r0;     bfl[2 * p][1] = r2;
                    bfl[2 * p + 1][0] = r1; bfl[2 * p + 1][1] = r3;
                }
#pragma unroll
                for (int mt = 0; mt < 4; ++mt)
#pragma unroll
                    for (int ntl = 0; ntl < 4; ++ntl)
                        MMA16816H(ccr[mt][ntl], afh[mt], bfl[ntl][0], bfl[ntl][1]);
            }

            if (st < 15) {
                char* base = smem + (buf ^ 1) * BUF_B;
#pragma unroll
                for (int i = 0; i < 4; ++i) {
                    uint2 hi, lo; split4s(av[i], hi, lo);
                    *(uint2*)(base + asts[i])              = hi;
                    *(uint2*)(base + TILE_B + asts[i])     = lo;
                    *(uint2*)(base + 2 * TILE_B + asts[i]) = bh[i];
                    *(uint2*)(base + 3 * TILE_B + asts[i]) = bl[i];
                }
            }
            __syncthreads();
        }

        // ---- fused epilogue: rowacc += (Chh + 2^-12 Ccr) .* (Enc .* hid) ----
        // f16-acc layout: reg0 = {c0,c1} (row lane>>2), reg1 = {c2,c3} (row +8)
#pragma unroll
        for (int mt = 0; mt < 4; ++mt) {
#pragma unroll
            for (int j = 0; j < 2; ++j) {
                const int r = m0 + warp_m * 64 + mt * 16 + (lane >> 2) + j * 8;
                const float* er = enc + (size_t)r * H_DIM;
                const float* hr = hid + (size_t)(r & 31) * H_DIM;
                float acc = 0.f;
#pragma unroll
                for (int ntl = 0; ntl < 4; ++ntl) {
                    const int col = nbase + warp_n * 32 + ntl * 8 + (lane & 3) * 2;
                    const float2 e = *(const float2*)(er + col);
                    const float2 h = *(const float2*)(hr + col);
                    const float2 cr = __half22float2(*(__half2*)&ccr[mt][ntl][j]);
                    const float c0 = chh[mt][ntl][j * 2 + 0] + INV_CROSS * cr.x;
                    const float c1 = chh[mt][ntl][j * 2 + 1] + INV_CROSS * cr.y;
                    acc = fmaf(c0, e.x * h.x, acc);
                    acc = fmaf(c1, e.y * h.y, acc);
                }
                rowacc[mt][j] += acc;
            }
        }
        __syncthreads();   // all reads of buffers done before next nt prologue STS
    }

    // ---- reduce: quad lanes (cols) -> shared rows -> global ----
    float* srow = (float*)smem;
    if (tid < 128) srow[tid] = 0.f;
    __syncthreads();
#pragma unroll
    for (int mt = 0; mt < 4; ++mt)
#pragma unroll
        for (int j = 0; j < 2; ++j) {
            float v = rowacc[mt][j];
            v += __shfl_xor_sync(0xffffffffu, v, 1);
            v += __shfl_xor_sync(0xffffffffu, v, 2);
            if ((lane & 3) == 0)
                atomicAdd(&srow[warp_m * 64 + mt * 16 + (lane >> 2) + j * 8], v);
        }
    __syncthreads();
    if (tid < 128) {
        const int r = m0 + tid;
        logits[(r & 31) * S_LEN + (r >> 5)] = srow[tid];   // out[b*4096 + s]
    }
}

// ---------------- kernel 2: affect term + s==0 fixup + softmax ----------------
__global__ __launch_bounds__(256) void softmax_finalize(
    const float* __restrict__ enc, const float* __restrict__ hid,
    const float* __restrict__ emb, const float* __restrict__ aff,
    float* __restrict__ out)
{
    const int b = blockIdx.x;
    const int tid = threadIdx.x;
    const int lane = tid & 31, wid = tid >> 5;
    __shared__ float red[8][4];
    __shared__ float fin[4];
    __shared__ float rmax[8];
    __shared__ float rsum[8];

    float a0 = 0.f, a1 = 0.f, a2 = 0.f, e0 = 0.f;
    for (int h = tid; h < H_DIM; h += 256) {
        const float hv = hid[b * H_DIM + h];
        a0 += hv * aff[h * 3 + 0];
        a1 += hv * aff[h * 3 + 1];
        a2 += hv * aff[h * 3 + 2];
        e0 += hv * enc[b * H_DIM + h];
    }
#pragma unroll
    for (int m = 16; m; m >>= 1) {
        a0 += __shfl_xor_sync(~0u, a0, m);
        a1 += __shfl_xor_sync(~0u, a1, m);
        a2 += __shfl_xor_sync(~0u, a2, m);
        e0 += __shfl_xor_sync(~0u, e0, m);
    }
    if (lane == 0) { red[wid][0] = a0; red[wid][1] = a1; red[wid][2] = a2; red[wid][3] = e0; }
    __syncthreads();
    if (tid < 4) {
        float s = 0.f;
        for (int w = 0; w < 8; ++w) s += red[w][tid];
        fin[tid] = s;
    }
    __syncthreads();
    const float A0 = fin[0], A1 = fin[1], A2 = fin[2], E0 = fin[3];

    float l[16];
    float mx = -INFINITY;
#pragma unroll
    for (int it = 0; it < 16; ++it) {
        const int s = tid + it * 256;
        float v = (s == 0) ? E0 : out[b * S_LEN + s];
        const float* ep = emb + ((size_t)s * B_DIM + b) * 3;
        v += A0 * ep[0] + A1 * ep[1] + A2 * ep[2];
        l[it] = v;
        mx = fmaxf(mx, v);
    }
#pragma unroll
    for (int m = 16; m; m >>= 1) mx = fmaxf(mx, __shfl_xor_sync(~0u, mx, m));
    if (lane == 0) rmax[wid] = mx;
    __syncthreads();
    if (tid == 0) {
        float m2 = rmax[0];
        for (int w = 1; w < 8; ++w) m2 = fmaxf(m2, rmax[w]);
        rmax[0] = m2;
    }
    __syncthreads();
    const float MX = rmax[0];

    float sum = 0.f;
#pragma unroll
    for (int it = 0; it < 16; ++it) { l[it] = expf(l[it] - MX); sum += l[it]; }
#pragma unroll
    for (int m = 16; m; m >>= 1) sum += __shfl_xor_sync(~0u, sum, m);
    if (lane == 0) rsum[wid] = sum;
    __syncthreads();
    if (tid == 0) {
        float s2 = 0.f;
        for (int w = 0; w < 8; ++w) s2 += rsum[w];
        rsum[0] = s2;
    }
    __syncthreads();
    const float inv = 1.0f / rsum[0];
#pragma unroll
    for (int it = 0; it < 16; ++it)
        out[b * S_LEN + tid + it * 256] = l[it] * inv;
}

// ---------------- launch ----------------
extern "C" void kernel_launch(void* const* d_in, const int* in_sizes, int n_in,
                              void* d_out, int out_size) {
    const float *hid = nullptr, *enc = nullptr, *emb = nullptr, *Wm = nullptr, *aff = nullptr;
    for (int i = 0; i < n_in; ++i) {
        switch (in_sizes[i]) {
            case 16384:    hid = (const float*)d_in[i]; break;  // hidden [1,32,512]
            case 67108864: enc = (const float*)d_in[i]; break;  // encoder_outputs [4096,32,512]
            case 393216:   emb = (const float*)d_in[i]; break;  // embedding [4096,32,3]
            case 262144:   Wm  = (const float*)d_in[i]; break;  // bigram_matrix [512,512]
            case 1536:     aff = (const float*)d_in[i]; break;  // affect_matrix [512,3]
        }
    }
    float* out = (float*)d_out;  // [32,1,4096] fp32; logits scratch then softmax

    cudaFuncSetAttribute(bilinear_hmma,
                         cudaFuncAttributeMaxDynamicSharedMemorySize, SMEM_TOTAL);

    split_w<<<(H_DIM * H_DIM) / 256, 256>>>(Wm);
    bilinear_hmma<<<(S_LEN * B_DIM) / 128, 256, SMEM_TOTAL>>>(enc, hid, out);
    softmax_finalize<<<B_DIM, 256>>>(enc, hid, emb, aff, out);
}

// round 15
// speedup vs baseline: 3.8122x; 1.0443x over previous
#include <cuda_runtime.h>
#include <cuda_fp16.h>
#include <math.h>
#include <stdint.h>

#define S_LEN 4096
#define B_DIM 32
#define H_DIM 512
#define NROW  (S_LEN * B_DIM)   // 131072

// packing scales: P = 32*Ah + 4096*Al ; Q = 32*Wh + 4096*Wl
// Cpq = 1024*Ah@Wh + 131072*cross + 2^24*lolo
// C   = 0.9921875*C1 + Cpq/131072
#define C1_COEF  0.9921875f
#define CPQ_COEF 7.62939453125e-06f   // 1/131072

// ---------------- device scratch: transposed fp16 planes of W ----------------
// g_Bh[n*512+k] = hi(W[k][n]);  g_Bq = fp16(32*Wh + 4096*(W - Wh))
__device__ __half g_Bh[H_DIM * H_DIM];
__device__ __half g_Bq[H_DIM * H_DIM];

__device__ __forceinline__ uint32_t smem_u32(const void* p) {
    uint32_t a;
    asm("{ .reg .u64 t; cvta.to.shared.u64 t, %1; cvt.u32.u64 %0, t; }" : "=r"(a) : "l"(p));
    return a;
}

#define LDSM4(r0, r1, r2, r3, addr) \
    asm volatile("ldmatrix.sync.aligned.m8n8.x4.shared.b16 {%0,%1,%2,%3}, [%4];" \
        : "=r"(r0), "=r"(r1), "=r"(r2), "=r"(r3) : "r"(addr))

#define MMA16816(c, a, b0, b1) \
    asm volatile("mma.sync.aligned.m16n8k16.row.col.f32.f16.f16.f32 " \
        "{%0,%1,%2,%3}, {%4,%5,%6,%7}, {%8,%9}, {%0,%1,%2,%3};" \
        : "+f"((c)[0]), "+f"((c)[1]), "+f"((c)[2]), "+f"((c)[3]) \
        : "r"((a)[0]), "r"((a)[1]), "r"((a)[2]), "r"((a)[3]), "r"(b0), "r"(b1))

// ---------------- kernel 0: split W into (hi, packed-q) transposed ----------
__global__ __launch_bounds__(256) void split_w(const float* __restrict__ Wm) {
    int idx = blockIdx.x * 256 + threadIdx.x;   // 0 .. 262143
    int k = idx >> 9, n = idx & 511;
    float v = Wm[idx];
    __half hi = __float2half_rn(v);
    float hif = __half2float(hi);
    g_Bh[n * H_DIM + k] = hi;
    g_Bq[n * H_DIM + k] = __float2half_rn(32.0f * hif + 4096.0f * (v - hif));
}

// produce (hi, packed-q) fp16x2 pairs from a float4
__device__ __forceinline__ void split4q(float4 v, uint2& hi, uint2& qq) {
    __half2 h01 = __floats2half2_rn(v.x, v.y);
    __half2 h23 = __floats2half2_rn(v.z, v.w);
    float2 f01 = __half22float2(h01);
    float2 f23 = __half22float2(h23);
    __half2 q01 = __floats2half2_rn(32.0f * f01.x + 4096.0f * (v.x - f01.x),
                                    32.0f * f01.y + 4096.0f * (v.y - f01.y));
    __half2 q23 = __floats2half2_rn(32.0f * f23.x + 4096.0f * (v.z - f23.x),
                                    32.0f * f23.y + 4096.0f * (v.w - f23.y));
    hi.x = *(uint32_t*)&h01; hi.y = *(uint32_t*)&h23;
    qq.x = *(uint32_t*)&q01; qq.y = *(uint32_t*)&q23;
}

// ---------------- kernel 1: 2-GEMM packed-split bilinear -> logits -----------
// rows r = s*32+b; A[m] = Enc[r-32] (rows r<32 garbage, fixed by kernel 2)
// C1 = Ah@Wh ; Cpq = P@Q ; C = C1_COEF*C1 + CPQ_COEF*Cpq
// logit[r] = sum_n C[r,n] * Enc[r,n] * hid[b,n]
//
// SMEM per buffer: 4 tiles (A_hi, A_q, B_hi, B_q), 128 rows x 40 halfs (80B)
#define TSTRIDE_B 80
#define TILE_B    (128 * TSTRIDE_B)   // 10240
#define BUF_B     (4 * TILE_B)        // 40960
#define SMEM_TOTAL (2 * BUF_B)        // 81920

__global__ __launch_bounds__(256, 1) void bilinear_hmma(
    const float* __restrict__ enc, const float* __restrict__ hid,
    float* __restrict__ logits)
{
    extern __shared__ char smem[];
    const uint32_t sb = smem_u32(smem);
    const int tid = threadIdx.x;
    const int lane = tid & 31, wid = tid >> 5;
    const int warp_m = wid >> 2;     // 0..1 : m offset 64*warp_m
    const int warp_n = wid & 3;      // 0..3 : n offset 32*warp_n
    const int m0 = blockIdx.x * 128;

    // ---- fill mapping: slot = tid + i*256; row = slot>>3; c4 = (slot&7)*4 ----
    const int rrow = tid >> 3;           // 0..31
    const int c4   = (tid & 7) * 4;      // 0,4,..,28
    const float* aptr[4];
    uint32_t asts[4];
#pragma unroll
    for (int i = 0; i < 4; ++i) {
        const int row = rrow + i * 32;
        long gr = (long)m0 + row - B_DIM; if (gr < 0) gr = 0;
        aptr[i] = enc + (size_t)gr * H_DIM + c4;
        asts[i] = (uint32_t)(row * TSTRIDE_B + c4 * 2);
    }

    // ---- ldmatrix addresses ----
    uint32_t a_addr[4];
#pragma unroll
    for (int mt = 0; mt < 4; ++mt)
        a_addr[mt] = sb + (uint32_t)((warp_m * 64 + mt * 16 + (lane & 15)) * TSTRIDE_B
                                     + ((lane >> 4) & 1) * 16);
    uint32_t b_addr[2];
#pragma unroll
    for (int p = 0; p < 2; ++p)
        b_addr[p] = sb + 2 * TILE_B + (uint32_t)((warp_n * 32 + p * 16 + (lane & 15)) * TSTRIDE_B
                                                 + ((lane >> 4) & 1) * 16);

    float rowacc[4][2];
#pragma unroll
    for (int mt = 0; mt < 4; ++mt) { rowacc[mt][0] = 0.f; rowacc[mt][1] = 0.f; }

#pragma unroll 1
    for (int nt = 0; nt < 4; ++nt) {
        const int nbase = nt * 128;

        float chh[4][4][4];   // Ah@Wh
        float cpq[4][4][4];   // P@Q
#pragma unroll
        for (int mt = 0; mt < 4; ++mt)
#pragma unroll
            for (int ntl = 0; ntl < 4; ++ntl)
#pragma unroll
                for (int q = 0; q < 4; ++q) { chh[mt][ntl][q] = 0.f; cpq[mt][ntl][q] = 0.f; }

        float4 av[4];
        uint2 bh[4], bq[4];

        // ---- prologue: LDG + STS stage 0 -> buf 0 ----
#pragma unroll
        for (int i = 0; i < 4; ++i) av[i] = *(const float4*)(aptr[i]);
#pragma unroll
        for (int i = 0; i < 4; ++i) {
            const size_t o = (size_t)(nbase + rrow + i * 32) * H_DIM + c4;
            bh[i] = *(const uint2*)(g_Bh + o);
            bq[i] = *(const uint2*)(g_Bq + o);
        }
        {
            char* base = smem;
#pragma unroll
            for (int i = 0; i < 4; ++i) {
                uint2 hi, qq; split4q(av[i], hi, qq);
                *(uint2*)(base + asts[i])              = hi;
                *(uint2*)(base + TILE_B + asts[i])     = qq;
                *(uint2*)(base + 2 * TILE_B + asts[i]) = bh[i];
                *(uint2*)(base + 3 * TILE_B + asts[i]) = bq[i];
            }
        }
        __syncthreads();

#pragma unroll 1
        for (int st = 0; st < 16; ++st) {
            const int buf = st & 1;
            if (st < 15) {
                const int kb = (st + 1) * 32;
#pragma unroll
                for (int i = 0; i < 4; ++i) av[i] = *(const float4*)(aptr[i] + kb);
#pragma unroll
                for (int i = 0; i < 4; ++i) {
                    const size_t o = (size_t)(nbase + rrow + i * 32) * H_DIM + kb + c4;
                    bh[i] = *(const uint2*)(g_Bh + o);
                    bq[i] = *(const uint2*)(g_Bq + o);
                }
            }

            const uint32_t boff = buf ? (uint32_t)BUF_B : 0u;
#pragma unroll
            for (int kk = 0; kk < 2; ++kk) {
                const uint32_t koff = boff + kk * 32;   // 16 halfs = 32B per k16
                uint32_t af[4][4];
                uint32_t bf[4][2];
                // ---- GEMM 1: Ah @ Wh ----
#pragma unroll
                for (int mt = 0; mt < 4; ++mt)
                    LDSM4(af[mt][0], af[mt][1], af[mt][2], af[mt][3], a_addr[mt] + koff);
#pragma unroll
                for (int p = 0; p < 2; ++p) {
                    uint32_t r0, r1, r2, r3;
                    LDSM4(r0, r1, r2, r3, b_addr[p] + koff);
                    bf[2 * p][0] = r0;     bf[2 * p][1] = r2;
                    bf[2 * p + 1][0] = r1; bf[2 * p + 1][1] = r3;
                }
#pragma unroll
                for (int mt = 0; mt < 4; ++mt)
#pragma unroll
                    for (int ntl = 0; ntl < 4; ++ntl)
                        MMA16816(chh[mt][ntl], af[mt], bf[ntl][0], bf[ntl][1]);
                // ---- GEMM 2: P @ Q (packed tiles at +TILE_B) ----
#pragma unroll
                for (int mt = 0; mt < 4; ++mt)
                    LDSM4(af[mt][0], af[mt][1], af[mt][2], af[mt][3],
                          a_addr[mt] + koff + TILE_B);
#pragma unroll
                for (int p = 0; p < 2; ++p) {
                    uint32_t r0, r1, r2, r3;
                    LDSM4(r0, r1, r2, r3, b_addr[p] + koff + TILE_B);
                    bf[2 * p][0] = r0;     bf[2 * p][1] = r2;
                    bf[2 * p + 1][0] = r1; bf[2 * p + 1][1] = r3;
                }
#pragma unroll
                for (int mt = 0; mt < 4; ++mt)
#pragma unroll
                    for (int ntl = 0; ntl < 4; ++ntl)
                        MMA16816(cpq[mt][ntl], af[mt], bf[ntl][0], bf[ntl][1]);
            }

            if (st < 15) {
                char* base = smem + (buf ^ 1) * BUF_B;
#pragma unroll
                for (int i = 0; i < 4; ++i) {
                    uint2 hi, qq; split4q(av[i], hi, qq);
                    *(uint2*)(base + asts[i])              = hi;
                    *(uint2*)(base + TILE_B + asts[i])     = qq;
                    *(uint2*)(base + 2 * TILE_B + asts[i]) = bh[i];
                    *(uint2*)(base + 3 * TILE_B + asts[i]) = bq[i];
                }
            }
            __syncthreads();
        }

        // ---- fused epilogue: rowacc += (C1_COEF*chh + CPQ_COEF*cpq) .* (Enc.*hid) ----
#pragma unroll
        for (int mt = 0; mt < 4; ++mt) {
#pragma unroll
            for (int j = 0; j < 2; ++j) {
                const int r = m0 + warp_m * 64 + mt * 16 + (lane >> 2) + j * 8;
                const float* er = enc + (size_t)r * H_DIM;
                const float* hr = hid + (size_t)(r & 31) * H_DIM;
                float acc = 0.f;
#pragma unroll
                for (int ntl = 0; ntl < 4; ++ntl) {
                    const int col = nbase + warp_n * 32 + ntl * 8 + (lane & 3) * 2;
                    const float2 e = *(const float2*)(er + col);
                    const float2 h = *(const float2*)(hr + col);
                    const float c0 = fmaf(cpq[mt][ntl][j * 2 + 0], CPQ_COEF,
                                          C1_COEF * chh[mt][ntl][j * 2 + 0]);
                    const float c1 = fmaf(cpq[mt][ntl][j * 2 + 1], CPQ_COEF,
                                          C1_COEF * chh[mt][ntl][j * 2 + 1]);
                    acc = fmaf(c0, e.x * h.x, acc);
                    acc = fmaf(c1, e.y * h.y, acc);
                }
                rowacc[mt][j] += acc;
            }
        }
        __syncthreads();   // all reads of buffers done before next nt prologue STS
    }

    // ---- reduce: quad lanes (cols) -> shared rows -> global ----
    float* srow = (float*)smem;
    if (tid < 128) srow[tid] = 0.f;
    __syncthreads();
#pragma unroll
    for (int mt = 0; mt < 4; ++mt)
#pragma unroll
        for (int j = 0; j < 2; ++j) {
            float v = rowacc[mt][j];
            v += __shfl_xor_sync(0xffffffffu, v, 1);
            v += __shfl_xor_sync(0xffffffffu, v, 2);
            if ((lane & 3) == 0)
                atomicAdd(&srow[warp_m * 64 + mt * 16 + (lane >> 2) + j * 8], v);
        }
    __syncthreads();
    if (tid < 128) {
        const int r = m0 + tid;
        logits[(r & 31) * S_LEN + (r >> 5)] = srow[tid];   // out[b*4096 + s]
    }
}

// ---------------- kernel 2: affect term + s==0 fixup + softmax ----------------
__global__ __launch_bounds__(256) void softmax_finalize(
    const float* __restrict__ enc, const float* __restrict__ hid,
    const float* __restrict__ emb, const float* __restrict__ aff,
    float* __restrict__ out)
{
    const int b = blockIdx.x;
    const int tid = threadIdx.x;
    const int lane = tid & 31, wid = tid >> 5;
    __shared__ float red[8][4];
    __shared__ float fin[4];
    __shared__ float rmax[8];
    __shared__ float rsum[8];

    float a0 = 0.f, a1 = 0.f, a2 = 0.f, e0 = 0.f;
    for (int h = tid; h < H_DIM; h += 256) {
        const float hv = hid[b * H_DIM + h];
        a0 += hv * aff[h * 3 + 0];
        a1 += hv * aff[h * 3 + 1];
        a2 += hv * aff[h * 3 + 2];
        e0 += hv * enc[b * H_DIM + h];
    }
#pragma unroll
    for (int m = 16; m; m >>= 1) {
        a0 += __shfl_xor_sync(~0u, a0, m);
        a1 += __shfl_xor_sync(~0u, a1, m);
        a2 += __shfl_xor_sync(~0u, a2, m);
        e0 += __shfl_xor_sync(~0u, e0, m);
    }
    if (lane == 0) { red[wid][0] = a0; red[wid][1] = a1; red[wid][2] = a2; red[wid][3] = e0; }
    __syncthreads();
    if (tid < 4) {
        float s = 0.f;
        for (int w = 0; w < 8; ++w) s += red[w][tid];
        fin[tid] = s;
    }
    __syncthreads();
    const float A0 = fin[0], A1 = fin[1], A2 = fin[2], E0 = fin[3];

    float l[16];
    float mx = -INFINITY;
#pragma unroll
    for (int it = 0; it < 16; ++it) {
        const int s = tid + it * 256;
        float v = (s == 0) ? E0 : out[b * S_LEN + s];
        const float* ep = emb + ((size_t)s * B_DIM + b) * 3;
        v += A0 * ep[0] + A1 * ep[1] + A2 * ep[2];
        l[it] = v;
        mx = fmaxf(mx, v);
    }
#pragma unroll
    for (int m = 16; m; m >>= 1) mx = fmaxf(mx, __shfl_xor_sync(~0u, mx, m));
    if (lane == 0) rmax[wid] = mx;
    __syncthreads();
    if (tid == 0) {
        float m2 = rmax[0];
        for (int w = 1; w < 8; ++w) m2 = fmaxf(m2, rmax[w]);
        rmax[0] = m2;
    }
    __syncthreads();
    const float MX = rmax[0];

    float sum = 0.f;
#pragma unroll
    for (int it = 0; it < 16; ++it) { l[it] = expf(l[it] - MX); sum += l[it]; }
#pragma unroll
    for (int m = 16; m; m >>= 1) sum += __shfl_xor_sync(~0u, sum, m);
    if (lane == 0) rsum[wid] = sum;
    __syncthreads();
    if (tid == 0) {
        float s2 = 0.f;
        for (int w = 0; w < 8; ++w) s2 += rsum[w];
        rsum[0] = s2;
    }
    __syncthreads();
    const float inv = 1.0f / rsum[0];
#pragma unroll
    for (int it = 0; it < 16; ++it)
        out[b * S_LEN + tid + it * 256] = l[it] * inv;
}

// ---------------- launch ----------------
extern "C" void kernel_launch(void* const* d_in, const int* in_sizes, int n_in,
                              void* d_out, int out_size) {
    const float *hid = nullptr, *enc = nullptr, *emb = nullptr, *Wm = nullptr, *aff = nullptr;
    for (int i = 0; i < n_in; ++i) {
        switch (in_sizes[i]) {
            case 16384:    hid = (const float*)d_in[i]; break;  // hidden [1,32,512]
            case 67108864: enc = (const float*)d_in[i]; break;  // encoder_outputs [4096,32,512]
            case 393216:   emb = (const float*)d_in[i]; break;  // embedding [4096,32,3]
            case 262144:   Wm  = (const float*)d_in[i]; break;  // bigram_matrix [512,512]
            case 1536:     aff = (const float*)d_in[i]; break;  // affect_matrix [512,3]
        }
    }
    float* out = (float*)d_out;  // [32,1,4096] fp32; logits scratch then softmax

    cudaFuncSetAttribute(bilinear_hmma,
                         cudaFuncAttributeMaxDynamicSharedMemorySize, SMEM_TOTAL);

    split_w<<<(H_DIM * H_DIM) / 256, 256>>>(Wm);
    bilinear_hmma<<<(S_LEN * B_DIM) / 128, 256, SMEM_TOTAL>>>(enc, hid, out);
    softmax_finalize<<<B_DIM, 256>>>(enc, hid, emb, aff, out);
}